// round 15
// baseline (speedup 1.0000x reference)
#include <cuda_runtime.h>

#define RFN 512
#define TN  32
#define KN  32
#define LN  2048
#define LH  1024             // L per half (l-split x2)
#define BK  32               // f32 per tile = 2 ksteps of 16
#define NTILE (LH / BK)      // 32
#define STAGES 3
#define NCTA (RFN * 2)       // 1024: branch = bid>>1, half = bid&1

__device__ float g_part[NCTA][32][32];   // [cta][accidx][lane] 4 MB
__device__ int   g_cnt[RFN];             // per-branch tickets (reset after use)

// pack two f32 -> bf16x2 {hi, lo}
__device__ __forceinline__ unsigned cvt2(float hi, float lo) {
    unsigned r;
    asm("cvt.rn.bf16x2.f32 %0, %1, %2;" : "=r"(r) : "f"(hi), "f"(lo));
    return r;
}
__device__ __forceinline__ void cp_async16(unsigned dst, const float* src) {
    asm volatile("cp.async.cg.shared.global [%0], [%1], 16;" :: "r"(dst), "l"(src) : "memory");
}
// D += A*B, m16n8k16 bf16 -> f32 (baseline ISA, no sm_103a features)
__device__ __forceinline__ void mma16816(float* d, const unsigned* a, const unsigned* b) {
    asm volatile(
        "mma.sync.aligned.m16n8k16.row.col.f32.bf16.bf16.f32 "
        "{%0,%1,%2,%3}, {%4,%5,%6,%7}, {%8,%9}, {%0,%1,%2,%3};"
        : "+f"(d[0]), "+f"(d[1]), "+f"(d[2]), "+f"(d[3])
        : "r"(a[0]), "r"(a[1]), "r"(a[2]), "r"(a[3]), "r"(b[0]), "r"(b[1]));
}

struct Tri { unsigned h, m, l; };
__device__ __forceinline__ Tri split3(float2 v) {
    Tri t;
    t.h = cvt2(v.y, v.x);
    float hx = __uint_as_float(t.h << 16);
    float hy = __uint_as_float(t.h & 0xffff0000u);
    float rx = v.x - hx, ry = v.y - hy;
    t.m = cvt2(ry, rx);
    float mx = __uint_as_float(t.m << 16);
    float my = __uint_as_float(t.m & 0xffff0000u);
    t.l = cvt2(ry - my, rx - mx);
    return t;
}

// smem tile layout: 32 rows x 128B; 8B slot s of row r lives at ((s + 4r) & 15);
// 16B cp.async chunk c of row r -> ((c + 2r) & 7). (R14-proven conflict-free.)

__global__ __launch_bounds__(32)
void spyke_mma(const float* __restrict__ rec,   // (T=32, C=1, RF=512, L=2048)
               const float* __restrict__ Wt,    // (RF=512, K=32, C=1, L=2048)
               float* __restrict__ out)         // (T, 1, K, RF)
{
    __shared__ __align__(16) float As[STAGES][TN][BK];   // 4 KB / stage
    __shared__ __align__(16) float Bs[STAGES][KN][BK];

    const int lane = threadIdx.x;
    const int qr = lane >> 2;          // fragment row within 8-row group
    const int qc = lane & 3;           // fragment k-pair / col-pair selector
    const int r  = blockIdx.x >> 1;
    const int lb = (blockIdx.x & 1) * LH;

    const float* Abase = rec + (size_t)r * LN + lb;      // + t*RFN*LN
    const float* Bbase = Wt + (size_t)r * KN * LN + lb;  // + k*LN

    const unsigned sA = (unsigned)__cvta_generic_to_shared(&As[0][0][0]);
    const unsigned sB = (unsigned)__cvta_generic_to_shared(&Bs[0][0][0]);
    const char* cA = (const char*)&As[0][0][0];
    const char* cB = (const char*)&Bs[0][0][0];

    float acc[8][4];                   // [mt*4+nt][c0..c3]
#pragma unroll
    for (int i = 0; i < 8; i++)
#pragma unroll
        for (int j = 0; j < 4; j++) acc[i][j] = 0.0f;

    // ---- tile filler: 8 A + 8 B cp.async per lane, rotated 16B chunks ----
    auto fill = [&](int s, int l0) {
#pragma unroll
        for (int i = 0; i < 8; i++) {            // A: 256 chunks
            int idx = i * 32 + lane;
            int row = idx >> 3, c4 = idx & 7;
            unsigned soff = (unsigned)(s * 4096 + row * 128 + (((c4 + 2 * row) & 7) * 16));
            cp_async16(sA + soff, Abase + (size_t)row * (RFN * LN) + l0 + c4 * 4);
        }
#pragma unroll
        for (int i = 0; i < 8; i++) {            // B: 256 chunks
            int idx = i * 32 + lane;
            int row = idx >> 3, c4 = idx & 7;
            unsigned soff = (unsigned)(s * 4096 + row * 128 + (((c4 + 2 * row) & 7) * 16));
            cp_async16(sB + soff, Bbase + (size_t)row * LN + l0 + c4 * 4);
        }
        asm volatile("cp.async.commit_group;" ::: "memory");
    };

    fill(0, 0);
    fill(1, BK);

    int buf = 0, pf = STAGES - 1;
    for (int ti = 0; ti < NTILE; ti++) {
        asm volatile("cp.async.wait_group %0;" :: "n"(STAGES - 2) : "memory");
        __syncwarp();

        if (ti + STAGES - 1 < NTILE) {
            fill(pf, (ti + STAGES - 1) * BK);
        } else {
            asm volatile("cp.async.commit_group;" ::: "memory");
        }
        if (++pf == STAGES) pf = 0;

        const char* tA = cA + buf * 4096;
        const char* tB = cB + buf * 4096;
#pragma unroll
        for (int kk = 0; kk < 2; kk++) {
            const int s0 = kk * 8 + qc;          // base 8B slot

            // A fragments: 2 m-tiles x 4 pairs -> 3 split levels
            unsigned Ah[2][4], Am[2][4], Al[2][4];
#pragma unroll
            for (int mt = 0; mt < 2; mt++)
#pragma unroll
                for (int p = 0; p < 4; p++) {
                    int rr = mt * 16 + qr + (p & 1) * 8;
                    int ss = s0 + (p >> 1) * 4;
                    float2 v = *(const float2*)(tA + rr * 128 + (((ss + 4 * rr) & 15) * 8));
                    Tri t = split3(v);
                    Ah[mt][p] = t.h; Am[mt][p] = t.m; Al[mt][p] = t.l;
                }

            // B fragments: 4 n-tiles x 2 pairs -> 3 split levels
            unsigned Bh[4][2], Bm[4][2], Bl[4][2];
#pragma unroll
            for (int nt = 0; nt < 4; nt++)
#pragma unroll
                for (int p = 0; p < 2; p++) {
                    int rr = nt * 8 + qr;
                    int ss = s0 + p * 4;
                    float2 v = *(const float2*)(tB + rr * 128 + (((ss + 4 * rr) & 15) * 8));
                    Tri t = split3(v);
                    Bh[nt][p] = t.h; Bm[nt][p] = t.m; Bl[nt][p] = t.l;
                }

            // 6 split-products per tile: hh, hm, mh, mm, hl, lh
#pragma unroll
            for (int mt = 0; mt < 2; mt++)
#pragma unroll
                for (int nt = 0; nt < 4; nt++) {
                    float* d = acc[mt * 4 + nt];
                    mma16816(d, Ah[mt], Bh[nt]);
                    mma16816(d, Ah[mt], Bm[nt]);
                    mma16816(d, Am[mt], Bh[nt]);
                    mma16816(d, Am[mt], Bm[nt]);
                    mma16816(d, Ah[mt], Bl[nt]);
                    mma16816(d, Al[mt], Bh[nt]);
                }
        }
        if (++buf == STAGES) buf = 0;
    }

    // ---- store partial fragments (coalesced: 32 lanes x 4B per accidx) ----
    {
        float* dst = &g_part[blockIdx.x][0][0];
#pragma unroll
        for (int i = 0; i < 8; i++)
#pragma unroll
            for (int j = 0; j < 4; j++)
                dst[(i * 4 + j) * 32 + lane] = acc[i][j];
    }

    __threadfence();
    int old = 0;
    if (lane == 0) old = atomicAdd(&g_cnt[r], 1);
    old = __shfl_sync(0xffffffffu, old, 0);
    if (old != 1) return;
    __threadfence();   // acquire: both halves' partials visible

    // ---- finisher: combine halves into this warp's own fragment layout ----
    const float* p0 = &g_part[r * 2 + 0][0][0];
    const float* p1 = &g_part[r * 2 + 1][0][0];
#pragma unroll
    for (int i = 0; i < 8; i++)
#pragma unroll
        for (int j = 0; j < 4; j++)
            acc[i][j] = p0[(i * 4 + j) * 32 + lane] + p1[(i * 4 + j) * 32 + lane];

    // ---- threshold, scatter C fragments to thr[t][33] in (dead) tile smem ----
    float* thr_sh = &As[0][0][0];     // 32*33 floats, spills into As[1] (dead)
    __syncwarp();
#pragma unroll
    for (int mt = 0; mt < 2; mt++)
#pragma unroll
        for (int nt = 0; nt < 4; nt++) {
            const float* c = acc[mt * 4 + nt];
            int t0 = mt * 16 + qr;
            int k0 = nt * 8 + 2 * qc;
            thr_sh[t0 * 33 + k0]           = (c[0] > 20.0f) ? c[0] : 0.0f;
            thr_sh[t0 * 33 + k0 + 1]       = (c[1] > 20.0f) ? c[1] : 0.0f;
            thr_sh[(t0 + 8) * 33 + k0]     = (c[2] > 20.0f) ? c[2] : 0.0f;
            thr_sh[(t0 + 8) * 33 + k0 + 1] = (c[3] > 20.0f) ? c[3] : 0.0f;
        }
    __syncwarp();

    // ---- kWTA (R5-verbatim; lane = feature k) ----
    float th[TN];
    int cnt = 0;
#pragma unroll
    for (int t = 0; t < TN; t++) {
        th[t] = thr_sh[t * 33 + lane];
        cnt += (th[t] > 0.0f) ? 1 : 0;
    }
    int first = 32 - cnt;
    if (first > 31) first = 31;        // cnt==0 -> 31 ; cnt>=1 -> 0..31
    float vals = thr_sh[first * 33 + lane];
    float vk = (cnt > 0) ? vals : 0.0f;
    float vmax = vk;
#pragma unroll
    for (int o = 16; o > 0; o >>= 1) {
        float ov = __shfl_xor_sync(0xffffffffu, vmax, o);
        vmax = (ov > vmax) ? ov : vmax;
    }
    const float v = vmax * 32.0f;
    const float total = (float)cnt * (vals + v);

    float cur = total;
    bool win = false;
#pragma unroll
    for (int it = 0; it < 4; it++) {
        float bvv = cur;
        int bi = lane;
#pragma unroll
        for (int o = 16; o > 0; o >>= 1) {
            float ov = __shfl_xor_sync(0xffffffffu, bvv, o);
            int   oi = __shfl_xor_sync(0xffffffffu, bi, o);
            if (ov > bvv || (ov == bvv && oi < bi)) { bvv = ov; bi = oi; }
        }
        if (lane == bi) {
            if (cur > 0.0f) win = true;  // valid = top_val != 0
            cur = -1.0f;
        }
    }

    // ---- out[t,0,k,r] = (thr>0 && k is winner) ? 1 : 0 ----
#pragma unroll
    for (int t = 0; t < TN; t++) {
        out[(size_t)t * (KN * RFN) + (size_t)lane * RFN + r] =
            (win && th[t] > 0.0f) ? 1.0f : 0.0f;
    }

    if (lane == 0) g_cnt[r] = 0;       // reset for next graph replay
}

extern "C" void kernel_launch(void* const* d_in, const int* in_sizes, int n_in,
                              void* d_out, int out_size) {
    const float* rec = (const float*)d_in[0];   // rec_field (32,1,512,2048)
    const float* Wt  = (const float*)d_in[1];   // W (512,32,1,2048)
    // d_in[2] = reward — unused by the reference output
    float* out = (float*)d_out;                 // (32,1,32,512)
    spyke_mma<<<NCTA, 32>>>(rec, Wt, out);
}

// round 16
// speedup vs baseline: 1.1061x; 1.1061x over previous
#include <cuda_runtime.h>

#define RFN 512
#define TN  32
#define KN  32
#define LN  2048
#define BK  32               // f32 per tile = 2 ksteps of 16
#define NTILE (LN / BK)      // 64
#define STAGES 3

__device__ __forceinline__ void cp_async16(unsigned dst, const float* src) {
    asm volatile("cp.async.cg.shared.global [%0], [%1], 16;" :: "r"(dst), "l"(src) : "memory");
}
// D += A*B, m16n8k16 fp16 -> f32 (baseline ISA)
__device__ __forceinline__ void mma16816(float* d, const unsigned* a, const unsigned* b) {
    asm volatile(
        "mma.sync.aligned.m16n8k16.row.col.f32.f16.f16.f32 "
        "{%0,%1,%2,%3}, {%4,%5,%6,%7}, {%8,%9}, {%0,%1,%2,%3};"
        : "+f"(d[0]), "+f"(d[1]), "+f"(d[2]), "+f"(d[3])
        : "r"(a[0]), "r"(a[1]), "r"(a[2]), "r"(a[3]), "r"(b[0]), "r"(b[1]));
}

// fp16 2-way split: v = h + l with ~22-24 bits total coverage
struct Duo { unsigned h, l; };
__device__ __forceinline__ Duo split2(float2 v) {
    Duo d;
    asm("cvt.rn.f16x2.f32 %0, %1, %2;" : "=r"(d.h) : "f"(v.y), "f"(v.x));
    float hx, hy;
    asm("{ .reg .b16 lo, hi;\n\t"
        "mov.b32 {lo, hi}, %2;\n\t"
        "cvt.f32.f16 %0, lo;\n\t"
        "cvt.f32.f16 %1, hi; }"
        : "=f"(hx), "=f"(hy) : "r"(d.h));
    asm("cvt.rn.f16x2.f32 %0, %1, %2;" : "=r"(d.l) : "f"(v.y - hy), "f"(v.x - hx));
    return d;
}

// smem tile layout: 32 rows x 128B; 8B slot s of row r lives at ((s + 4r) & 15);
// 16B cp.async chunk c of row r -> ((c + 2r) & 7). (R14-proven conflict-free.)

__global__ __launch_bounds__(32)
void spyke_mma(const float* __restrict__ rec,   // (T=32, C=1, RF=512, L=2048)
               const float* __restrict__ Wt,    // (RF=512, K=32, C=1, L=2048)
               float* __restrict__ out)         // (T, 1, K, RF)
{
    __shared__ __align__(16) float As[STAGES][TN][BK];   // 4 KB / stage
    __shared__ __align__(16) float Bs[STAGES][KN][BK];

    const int lane = threadIdx.x;
    const int qr = lane >> 2;          // fragment row within 8-row group
    const int qc = lane & 3;           // fragment k-pair / col-pair selector
    const int r  = blockIdx.x;

    const float* Abase = rec + (size_t)r * LN;          // + t*RFN*LN
    const float* Bbase = Wt + (size_t)r * KN * LN;      // + k*LN

    const unsigned sA = (unsigned)__cvta_generic_to_shared(&As[0][0][0]);
    const unsigned sB = (unsigned)__cvta_generic_to_shared(&Bs[0][0][0]);
    const char* cA = (const char*)&As[0][0][0];
    const char* cB = (const char*)&Bs[0][0][0];

    float acc[8][4];                   // [mt*4+nt][c0..c3]
#pragma unroll
    for (int i = 0; i < 8; i++)
#pragma unroll
        for (int j = 0; j < 4; j++) acc[i][j] = 0.0f;

    // ---- tile filler: 8 A + 8 B cp.async per lane, rotated 16B chunks ----
    auto fill = [&](int s, int l0) {
#pragma unroll
        for (int i = 0; i < 8; i++) {            // A: 256 chunks
            int idx = i * 32 + lane;
            int row = idx >> 3, c4 = idx & 7;
            unsigned soff = (unsigned)(s * 4096 + row * 128 + (((c4 + 2 * row) & 7) * 16));
            cp_async16(sA + soff, Abase + (size_t)row * (RFN * LN) + l0 + c4 * 4);
        }
#pragma unroll
        for (int i = 0; i < 8; i++) {            // B: 256 chunks
            int idx = i * 32 + lane;
            int row = idx >> 3, c4 = idx & 7;
            unsigned soff = (unsigned)(s * 4096 + row * 128 + (((c4 + 2 * row) & 7) * 16));
            cp_async16(sB + soff, Bbase + (size_t)row * LN + l0 + c4 * 4);
        }
        asm volatile("cp.async.commit_group;" ::: "memory");
    };

    fill(0, 0);
    fill(1, BK);

    int buf = 0, pf = STAGES - 1;
    for (int ti = 0; ti < NTILE; ti++) {
        asm volatile("cp.async.wait_group %0;" :: "n"(STAGES - 2) : "memory");
        __syncwarp();

        if (ti + STAGES - 1 < NTILE) {
            fill(pf, (ti + STAGES - 1) * BK);
        } else {
            asm volatile("cp.async.commit_group;" ::: "memory");
        }
        if (++pf == STAGES) pf = 0;

        const char* tA = cA + buf * 4096;
        const char* tB = cB + buf * 4096;
#pragma unroll
        for (int kk = 0; kk < 2; kk++) {
            const int s0 = kk * 8 + qc;          // base 8B slot

            // A fragments: 2 m-tiles x 4 pairs -> 2 split levels
            unsigned Ah[2][4], Al[2][4];
#pragma unroll
            for (int mt = 0; mt < 2; mt++)
#pragma unroll
                for (int p = 0; p < 4; p++) {
                    int rr = mt * 16 + qr + (p & 1) * 8;
                    int ss = s0 + (p >> 1) * 4;
                    float2 v = *(const float2*)(tA + rr * 128 + (((ss + 4 * rr) & 15) * 8));
                    Duo d = split2(v);
                    Ah[mt][p] = d.h; Al[mt][p] = d.l;
                }

            // B fragments: 4 n-tiles x 2 pairs -> 2 split levels
            unsigned Bh[4][2], Bl[4][2];
#pragma unroll
            for (int nt = 0; nt < 4; nt++)
#pragma unroll
                for (int p = 0; p < 2; p++) {
                    int rr = nt * 8 + qr;
                    int ss = s0 + p * 4;
                    float2 v = *(const float2*)(tB + rr * 128 + (((ss + 4 * rr) & 15) * 8));
                    Duo d = split2(v);
                    Bh[nt][p] = d.h; Bl[nt][p] = d.l;
                }

            // 3 split-products per tile: hh, hl, lh (ll ~ 2^-24, dropped)
#pragma unroll
            for (int mt = 0; mt < 2; mt++)
#pragma unroll
                for (int nt = 0; nt < 4; nt++) {
                    float* d = acc[mt * 4 + nt];
                    mma16816(d, Ah[mt], Bh[nt]);
                    mma16816(d, Ah[mt], Bl[nt]);
                    mma16816(d, Al[mt], Bh[nt]);
                }
        }
        if (++buf == STAGES) buf = 0;
    }

    // ---- threshold, scatter C fragments to thr[t][33] in (dead) tile smem ----
    float* thr_sh = &As[0][0][0];     // 32*33 floats, spills into As[1] (dead)
    __syncwarp();
#pragma unroll
    for (int mt = 0; mt < 2; mt++)
#pragma unroll
        for (int nt = 0; nt < 4; nt++) {
            const float* c = acc[mt * 4 + nt];
            int t0 = mt * 16 + qr;
            int k0 = nt * 8 + 2 * qc;
            thr_sh[t0 * 33 + k0]           = (c[0] > 20.0f) ? c[0] : 0.0f;
            thr_sh[t0 * 33 + k0 + 1]       = (c[1] > 20.0f) ? c[1] : 0.0f;
            thr_sh[(t0 + 8) * 33 + k0]     = (c[2] > 20.0f) ? c[2] : 0.0f;
            thr_sh[(t0 + 8) * 33 + k0 + 1] = (c[3] > 20.0f) ? c[3] : 0.0f;
        }
    __syncwarp();

    // ---- kWTA (R5-verbatim; lane = feature k) ----
    float th[TN];
    int cnt = 0;
#pragma unroll
    for (int t = 0; t < TN; t++) {
        th[t] = thr_sh[t * 33 + lane];
        cnt += (th[t] > 0.0f) ? 1 : 0;
    }
    int first = 32 - cnt;
    if (first > 31) first = 31;        // cnt==0 -> 31 ; cnt>=1 -> 0..31
    float vals = thr_sh[first * 33 + lane];
    float vk = (cnt > 0) ? vals : 0.0f;
    float vmax = vk;
#pragma unroll
    for (int o = 16; o > 0; o >>= 1) {
        float ov = __shfl_xor_sync(0xffffffffu, vmax, o);
        vmax = (ov > vmax) ? ov : vmax;
    }
    const float v = vmax * 32.0f;
    const float total = (float)cnt * (vals + v);

    float cur = total;
    bool win = false;
#pragma unroll
    for (int it = 0; it < 4; it++) {
        float bvv = cur;
        int bi = lane;
#pragma unroll
        for (int o = 16; o > 0; o >>= 1) {
            float ov = __shfl_xor_sync(0xffffffffu, bvv, o);
            int   oi = __shfl_xor_sync(0xffffffffu, bi, o);
            if (ov > bvv || (ov == bvv && oi < bi)) { bvv = ov; bi = oi; }
        }
        if (lane == bi) {
            if (cur > 0.0f) win = true;  // valid = top_val != 0
            cur = -1.0f;
        }
    }

    // ---- out[t,0,k,r] = (thr>0 && k is winner) ? 1 : 0 ----
#pragma unroll
    for (int t = 0; t < TN; t++) {
        out[(size_t)t * (KN * RFN) + (size_t)lane * RFN + r] =
            (win && th[t] > 0.0f) ? 1.0f : 0.0f;
    }
}

extern "C" void kernel_launch(void* const* d_in, const int* in_sizes, int n_in,
                              void* d_out, int out_size) {
    const float* rec = (const float*)d_in[0];   // rec_field (32,1,512,2048)
    const float* Wt  = (const float*)d_in[1];   // W (512,32,1,2048)
    // d_in[2] = reward — unused by the reference output
    float* out = (float*)d_out;                 // (32,1,32,512)
    spyke_mma<<<RFN, 32>>>(rec, Wt, out);
}

// round 17
// speedup vs baseline: 1.2200x; 1.1029x over previous
#include <cuda_runtime.h>

#define RFN 512
#define TN  32
#define KN  32
#define LN  2048
#define BK  32               // f32 per tile = 2 ksteps of 16
#define NTILE (LN / BK)      // 64
#define STAGES 4
#define THREADS 64           // 2 warps; warp w owns k-cols 16w..16w+15

__device__ __forceinline__ void cp_async16(unsigned dst, const float* src) {
    asm volatile("cp.async.cg.shared.global [%0], [%1], 16;" :: "r"(dst), "l"(src) : "memory");
}
// D += A*B, m16n8k16 fp16 -> f32 (baseline ISA)
__device__ __forceinline__ void mma16816(float* d, const unsigned* a, const unsigned* b) {
    asm volatile(
        "mma.sync.aligned.m16n8k16.row.col.f32.f16.f16.f32 "
        "{%0,%1,%2,%3}, {%4,%5,%6,%7}, {%8,%9}, {%0,%1,%2,%3};"
        : "+f"(d[0]), "+f"(d[1]), "+f"(d[2]), "+f"(d[3])
        : "r"(a[0]), "r"(a[1]), "r"(a[2]), "r"(a[3]), "r"(b[0]), "r"(b[1]));
}

// fp16 2-way split: v = h + l with ~22-24 bits total coverage
struct Duo { unsigned h, l; };
__device__ __forceinline__ Duo split2(float2 v) {
    Duo d;
    asm("cvt.rn.f16x2.f32 %0, %1, %2;" : "=r"(d.h) : "f"(v.y), "f"(v.x));
    float hx, hy;
    asm("{ .reg .b16 lo, hi;\n\t"
        "mov.b32 {lo, hi}, %2;\n\t"
        "cvt.f32.f16 %0, lo;\n\t"
        "cvt.f32.f16 %1, hi; }"
        : "=f"(hx), "=f"(hy) : "r"(d.h));
    asm("cvt.rn.f16x2.f32 %0, %1, %2;" : "=r"(d.l) : "f"(v.y - hy), "f"(v.x - hx));
    return d;
}

// smem tile layout: 32 rows x 128B; 8B slot s of row r lives at ((s + 4r) & 15);
// 16B cp.async chunk c of row r -> ((c + 2r) & 7). (R14-proven conflict-free.)

__global__ __launch_bounds__(THREADS)
void spyke_mma(const float* __restrict__ rec,   // (T=32, C=1, RF=512, L=2048)
               const float* __restrict__ Wt,    // (RF=512, K=32, C=1, L=2048)
               float* __restrict__ out)         // (T, 1, K, RF)
{
    __shared__ __align__(16) float As[STAGES][TN][BK];   // 4 KB / stage
    __shared__ __align__(16) float Bs[STAGES][KN][BK];

    const int tid  = threadIdx.x;
    const int wid  = tid >> 5;         // warp: n-half selector
    const int lane = tid & 31;
    const int qr = lane >> 2;          // fragment row within 8-row group
    const int qc = lane & 3;           // fragment k-pair / col-pair selector
    const int r  = blockIdx.x;

    const float* Abase = rec + (size_t)r * LN;          // + t*RFN*LN
    const float* Bbase = Wt + (size_t)r * KN * LN;      // + k*LN

    const unsigned sA = (unsigned)__cvta_generic_to_shared(&As[0][0][0]);
    const unsigned sB = (unsigned)__cvta_generic_to_shared(&Bs[0][0][0]);
    const char* cA = (const char*)&As[0][0][0];
    const char* cB = (const char*)&Bs[0][0][0];

    float acc[4][4];                   // [mt*2+nb][c0..c3], this warp's n-half
#pragma unroll
    for (int i = 0; i < 4; i++)
#pragma unroll
        for (int j = 0; j < 4; j++) acc[i][j] = 0.0f;

    // ---- tile filler: 4 A + 4 B cp.async per thread (64 threads) ----
    auto fill = [&](int s, int l0) {
#pragma unroll
        for (int i = 0; i < 4; i++) {            // A: 256 chunks
            int idx = i * 64 + tid;
            int row = idx >> 3, c4 = idx & 7;
            unsigned soff = (unsigned)(s * 4096 + row * 128 + (((c4 + 2 * row) & 7) * 16));
            cp_async16(sA + soff, Abase + (size_t)row * (RFN * LN) + l0 + c4 * 4);
        }
#pragma unroll
        for (int i = 0; i < 4; i++) {            // B: 256 chunks
            int idx = i * 64 + tid;
            int row = idx >> 3, c4 = idx & 7;
            unsigned soff = (unsigned)(s * 4096 + row * 128 + (((c4 + 2 * row) & 7) * 16));
            cp_async16(sB + soff, Bbase + (size_t)row * LN + l0 + c4 * 4);
        }
        asm volatile("cp.async.commit_group;" ::: "memory");
    };

    fill(0, 0);
    fill(1, BK);
    fill(2, 2 * BK);

    int buf = 0, pf = STAGES - 1;
    for (int ti = 0; ti < NTILE; ti++) {
        asm volatile("cp.async.wait_group %0;" :: "n"(STAGES - 2) : "memory");
        __syncthreads();   // tile ti visible; both warps past compute(ti-1)

        if (ti + STAGES - 1 < NTILE) {
            fill(pf, (ti + STAGES - 1) * BK);
        } else {
            asm volatile("cp.async.commit_group;" ::: "memory");
        }
        if (++pf == STAGES) pf = 0;

        const char* tA = cA + buf * 4096;
        const char* tB = cB + buf * 4096;
#pragma unroll
        for (int kk = 0; kk < 2; kk++) {
            const int s0 = kk * 8 + qc;          // base 8B slot

            // A fragments: 2 m-tiles x 4 pairs (computed by both warps)
            unsigned Ah[2][4], Al[2][4];
#pragma unroll
            for (int mt = 0; mt < 2; mt++)
#pragma unroll
                for (int p = 0; p < 4; p++) {
                    int rr = mt * 16 + qr + (p & 1) * 8;
                    int ss = s0 + (p >> 1) * 4;
                    float2 v = *(const float2*)(tA + rr * 128 + (((ss + 4 * rr) & 15) * 8));
                    Duo d = split2(v);
                    Ah[mt][p] = d.h; Al[mt][p] = d.l;
                }

            // B fragments: this warp's 2 n-tiles x 2 pairs
            unsigned Bh[2][2], Bl[2][2];
#pragma unroll
            for (int nb = 0; nb < 2; nb++)
#pragma unroll
                for (int p = 0; p < 2; p++) {
                    int rr = (2 * wid + nb) * 8 + qr;
                    int ss = s0 + p * 4;
                    float2 v = *(const float2*)(tB + rr * 128 + (((ss + 4 * rr) & 15) * 8));
                    Duo d = split2(v);
                    Bh[nb][p] = d.h; Bl[nb][p] = d.l;
                }

            // 3 split-products per tile: hh, hl, lh (ll ~ 2^-24, dropped)
#pragma unroll
            for (int mt = 0; mt < 2; mt++)
#pragma unroll
                for (int nb = 0; nb < 2; nb++) {
                    float* d = acc[mt * 2 + nb];
                    mma16816(d, Ah[mt], Bh[nb]);
                    mma16816(d, Ah[mt], Bl[nb]);
                    mma16816(d, Al[mt], Bh[nb]);
                }
        }
        if (++buf == STAGES) buf = 0;
    }

    // ---- threshold, scatter C fragments to thr[t][33] in (dead) tile smem ----
    __syncthreads();                   // all warps done with tile smem
    float* thr_sh = &As[0][0][0];      // 32*33 floats (dead stage buffers)
#pragma unroll
    for (int mt = 0; mt < 2; mt++)
#pragma unroll
        for (int nb = 0; nb < 2; nb++) {
            const float* c = acc[mt * 2 + nb];
            int t0 = mt * 16 + qr;
            int k0 = (2 * wid + nb) * 8 + 2 * qc;
            thr_sh[t0 * 33 + k0]           = (c[0] > 20.0f) ? c[0] : 0.0f;
            thr_sh[t0 * 33 + k0 + 1]       = (c[1] > 20.0f) ? c[1] : 0.0f;
            thr_sh[(t0 + 8) * 33 + k0]     = (c[2] > 20.0f) ? c[2] : 0.0f;
            thr_sh[(t0 + 8) * 33 + k0 + 1] = (c[3] > 20.0f) ? c[3] : 0.0f;
        }
    __syncthreads();

    // ---- kWTA (R5-verbatim; warp 0 only, lane = feature k) ----
    if (wid == 0) {
        float th[TN];
        int cnt = 0;
#pragma unroll
        for (int t = 0; t < TN; t++) {
            th[t] = thr_sh[t * 33 + lane];
            cnt += (th[t] > 0.0f) ? 1 : 0;
        }
        int first = 32 - cnt;
        if (first > 31) first = 31;    // cnt==0 -> 31 ; cnt>=1 -> 0..31
        float vals = thr_sh[first * 33 + lane];
        float vk = (cnt > 0) ? vals : 0.0f;
        float vmax = vk;
#pragma unroll
        for (int o = 16; o > 0; o >>= 1) {
            float ov = __shfl_xor_sync(0xffffffffu, vmax, o);
            vmax = (ov > vmax) ? ov : vmax;
        }
        const float v = vmax * 32.0f;
        const float total = (float)cnt * (vals + v);

        float cur = total;
        bool win = false;
#pragma unroll
        for (int it = 0; it < 4; it++) {
            float bvv = cur;
            int bi = lane;
#pragma unroll
            for (int o = 16; o > 0; o >>= 1) {
                float ov = __shfl_xor_sync(0xffffffffu, bvv, o);
                int   oi = __shfl_xor_sync(0xffffffffu, bi, o);
                if (ov > bvv || (ov == bvv && oi < bi)) { bvv = ov; bi = oi; }
            }
            if (lane == bi) {
                if (cur > 0.0f) win = true;  // valid = top_val != 0
                cur = -1.0f;
            }
        }

        // out[t,0,k,r] = (thr>0 && k is winner) ? 1 : 0
#pragma unroll
        for (int t = 0; t < TN; t++) {
            out[(size_t)t * (KN * RFN) + (size_t)lane * RFN + r] =
                (win && th[t] > 0.0f) ? 1.0f : 0.0f;
        }
    }
}

extern "C" void kernel_launch(void* const* d_in, const int* in_sizes, int n_in,
                              void* d_out, int out_size) {
    const float* rec = (const float*)d_in[0];   // rec_field (32,1,512,2048)
    const float* Wt  = (const float*)d_in[1];   // W (512,32,1,2048)
    // d_in[2] = reward — unused by the reference output
    float* out = (float*)d_out;                 // (32,1,32,512)
    spyke_mma<<<RFN, THREADS>>>(rec, Wt, out);
}